// round 15
// baseline (speedup 1.0000x reference)
#include <cuda_runtime.h>
#include <cuda_bf16.h>
#include <math.h>

// Problem constants
#define BB   2
#define SS   2048
#define DD   1024
#define HH   16
#define DK   64
#define HALF 64

// ---------------- scratch (device globals; no runtime allocation) ----------
__device__ float g_q[BB*HH*SS*DK];   // [B,H,S,DK] (tf32-rounded)
__device__ float g_k[BB*HH*SS*DK];
__device__ float g_v[BB*HH*SS*DK];
__device__ float g_x[BB*SS*DD];      // [B,S,D] attention output (tf32-rounded)
__device__ float g_cq[BB*SS*DD];     // tf32-rounded inputs
__device__ float g_ck[BB*SS*DD];
__device__ float g_cv[BB*SS*DD];
__device__ float g_wq[DD*DD];        // tf32-rounded transposed weights [n][k]
__device__ float g_wk[DD*DD];
__device__ float g_wv[DD*DD];
__device__ float g_wo[DD*DD];

// ---------------- helpers ----------------------------------------------------
__device__ __forceinline__ unsigned cvta_sh(const void* p) {
    return (unsigned)__cvta_generic_to_shared(p);
}
__device__ __forceinline__ unsigned cvt_tf32(float x) {
    unsigned r; asm("cvt.rna.tf32.f32 %0, %1;" : "=r"(r) : "f"(x)); return r;
}
__device__ __forceinline__ float round_tf32(float x) {
    return __uint_as_float(cvt_tf32(x));
}
#define CP_ASYNC16(saddr, gaddr) \
    asm volatile("cp.async.cg.shared.global [%0], [%1], 16;\n" :: "r"(saddr), "l"(gaddr))
#define CP_COMMIT() asm volatile("cp.async.commit_group;\n" ::)
#define CP_WAIT(N)  asm volatile("cp.async.wait_group %0;\n" :: "n"(N))

#define MMA_TF32(ac, a0,a1,a2,a3, b0,b1) \
    asm volatile( \
        "mma.sync.aligned.m16n8k8.row.col.f32.tf32.tf32.f32 " \
        "{%0,%1,%2,%3}, {%4,%5,%6,%7}, {%8,%9}, {%0,%1,%2,%3};" \
        : "+f"((ac)[0]), "+f"((ac)[1]), "+f"((ac)[2]), "+f"((ac)[3]) \
        : "r"(a0), "r"(a1), "r"(a2), "r"(a3), "r"(b0), "r"(b1))

#define LDSM4(r0,r1,r2,r3, addr) \
    asm volatile("ldmatrix.sync.aligned.m8n8.x4.shared.b16 {%0,%1,%2,%3}, [%4];" \
        : "=r"(r0), "=r"(r1), "=r"(r2), "=r"(r3) : "r"(addr))

// ---------------- band-skipping zero-fill (fully async side-stream) ----------
// Zeros every attn element with |j - qg| > HALF; never touches the band, so it
// has no ordering constraint against attn's band writes. Only needs to finish
// by graph end.
#define FILL_TOTAL4 ((size_t)BB * HH * SS * SS / 4)    // 33554432 float4
#define FILL_BLOCKS 128

__global__ __launch_bounds__(256) void fill_zero_kernel(float* __restrict__ dst)
{
    const float4 z4 = make_float4(0.f, 0.f, 0.f, 0.f);
    const size_t stride = (size_t)FILL_BLOCKS * 256;
    for (size_t i = (size_t)blockIdx.x * 256 + threadIdx.x; i < FILL_TOTAL4; i += stride) {
        int row = (int)(i >> 9);          // global row (bh*SS + qg)
        int qg  = row & (SS - 1);
        int j0  = (int)(i & 511) << 2;
        int lo  = qg - HALF, hi = qg + HALF;
        if (j0 > hi || j0 + 3 < lo) {
            __stcs(reinterpret_cast<float4*>(dst) + i, z4);
        } else if (j0 < lo || j0 + 3 > hi) {
            #pragma unroll
            for (int e = 0; e < 4; e++) {
                int j = j0 + e;
                if (j < lo || j > hi) __stcs(&dst[i * 4 + e], 0.f);
            }
        }
    }
}

// trivial terminator so the graph has a main-stream node after the join
__global__ void join_kernel() {}

// ---------------- fused prep: round inputs + transpose/round weights ---------
__global__ __launch_bounds__(256) void prep_kernel(
    const float* __restrict__ q, const float* __restrict__ k, const float* __restrict__ v,
    const float* __restrict__ Wq, const float* __restrict__ Wk,
    const float* __restrict__ Wv, const float* __restrict__ Wo)
{
    __shared__ float tile[32][33];
    int z = blockIdx.y;
    if (z < 3) {
        const float* src = (z == 0) ? q : (z == 1) ? k : v;
        float* dst = (z == 0) ? g_cq : (z == 1) ? g_ck : g_cv;
        size_t i = (size_t)blockIdx.x * 256 + threadIdx.x;
        float4 x = reinterpret_cast<const float4*>(src)[i];
        x.x = round_tf32(x.x); x.y = round_tf32(x.y);
        x.z = round_tf32(x.z); x.w = round_tf32(x.w);
        reinterpret_cast<float4*>(dst)[i] = x;
    } else {
        if (blockIdx.x >= 1024) return;
        int w = z - 3;
        const float* W = (w == 0) ? Wq : (w == 1) ? Wk : (w == 2) ? Wv : Wo;
        float* Wt      = (w == 0) ? g_wq : (w == 1) ? g_wk : (w == 2) ? g_wv : g_wo;
        int k0 = (blockIdx.x >> 5) * 32, n0 = (blockIdx.x & 31) * 32;
        int tx = threadIdx.x & 31, ty = threadIdx.x >> 5;
        #pragma unroll
        for (int j = 0; j < 32; j += 8)
            tile[ty + j][tx] = W[(size_t)(k0 + ty + j) * DD + n0 + tx];
        __syncthreads();
        #pragma unroll
        for (int j = 0; j < 32; j += 8)
            Wt[(size_t)(n0 + ty + j) * DD + k0 + tx] = round_tf32(tile[tx][ty + j]);
    }
}

// ---------------- TF32 GEMM: block 128x128, warp 64x32, BK=32, 3 stages ------
#define AS_STRIDE 36
#define BS_STRIDE 36
#define AS_STAGE  (128 * AS_STRIDE)
#define BS_STAGE  (128 * BS_STRIDE)
#define NSTAGE 3
#define SMEM_GEMM ((NSTAGE * (AS_STAGE + BS_STAGE)) * 4)   // 110592 B
#define NT (DD / 32)                                        // 32 k-iterations

__device__ __forceinline__ void gemm_load_stage(
    const float* __restrict__ A, const float* __restrict__ Wt,
    float* As, float* Bs, int stage, int k0, int m0, int n0, int tid)
{
    float* Ad = As + stage * AS_STAGE;
    float* Bd = Bs + stage * BS_STAGE;
    #pragma unroll
    for (int i = 0; i < 4; i++) {
        int f = tid + i * 256;
        int r = f >> 3, c4 = f & 7;
        CP_ASYNC16(cvta_sh(&Ad[r * AS_STRIDE + c4 * 4]),
                   &A[(size_t)(m0 + r) * DD + k0 + c4 * 4]);
    }
    #pragma unroll
    for (int i = 0; i < 4; i++) {
        int f = tid + i * 256;
        int r = f >> 3, c4 = f & 7;
        CP_ASYNC16(cvta_sh(&Bd[r * BS_STRIDE + c4 * 4]),
                   &Wt[(size_t)(n0 + r) * DD + k0 + c4 * 4]);
    }
    CP_COMMIT();
}

__device__ __forceinline__ void gemm_tf32(const float* __restrict__ A,
                                          const float* __restrict__ Wt,
                                          const float* __restrict__ bias,
                                          float* __restrict__ C,
                                          bool permuted)
{
    extern __shared__ float sm[];
    float* As = sm;
    float* Bs = sm + NSTAGE * AS_STAGE;

    const int tid  = threadIdx.x;
    const int lane = tid & 31;
    const int wid  = tid >> 5;
    const int wm   = wid >> 2;
    const int wn   = wid & 3;
    const int m0   = blockIdx.y * 128;
    const int n0   = blockIdx.x * 128;
    const int g    = lane >> 2;
    const int kq   = lane & 3;

    const int tIdx = lane >> 3;
    const int tRow = lane & 7;
    const unsigned a_base = cvta_sh(As) +
        (((wm * 64 + tRow + (tIdx & 1) * 8) * AS_STRIDE + (tIdx >> 1) * 4) << 2);
    const unsigned b_base = cvta_sh(Bs) +
        (((wn * 32 + tRow + (tIdx >> 1) * 8) * BS_STRIDE + (tIdx & 1) * 4) << 2);

    float acc[4][4][4];
    #pragma unroll
    for (int i = 0; i < 4; i++)
        #pragma unroll
        for (int j = 0; j < 4; j++)
            #pragma unroll
            for (int e = 0; e < 4; e++) acc[i][j][e] = 0.f;

    gemm_load_stage(A, Wt, As, Bs, 0, 0, m0, n0, tid);
    gemm_load_stage(A, Wt, As, Bs, 1, 32, m0, n0, tid);

    #pragma unroll 1
    for (int t = 0; t < NT; ++t) {
        if (t < NT - 1) { CP_WAIT(1); } else { CP_WAIT(0); }
        __syncthreads();

        if (t + 2 < NT)
            gemm_load_stage(A, Wt, As, Bs, (t + 2) % NSTAGE, (t + 2) * 32, m0, n0, tid);

        const int stg = t % NSTAGE;
        const unsigned aoff = a_base + (unsigned)(stg * AS_STAGE * 4);
        const unsigned boff = b_base + (unsigned)(stg * BS_STAGE * 4);

        #pragma unroll
        for (int kk = 0; kk < 4; ++kk) {
            unsigned a[4][4], b[4][2];
            #pragma unroll
            for (int mf = 0; mf < 4; ++mf)
                LDSM4(a[mf][0], a[mf][1], a[mf][2], a[mf][3],
                      aoff + (unsigned)(mf * 16 * AS_STRIDE * 4 + kk * 32));
            #pragma unroll
            for (int p = 0; p < 2; ++p)
                LDSM4(b[2*p][0], b[2*p][1], b[2*p+1][0], b[2*p+1][1],
                      boff + (unsigned)(p * 16 * BS_STRIDE * 4 + kk * 32));
            #pragma unroll
            for (int mf = 0; mf < 4; ++mf)
                #pragma unroll
                for (int nf = 0; nf < 4; ++nf)
                    MMA_TF32(acc[mf][nf], a[mf][0], a[mf][1], a[mf][2], a[mf][3],
                             b[nf][0], b[nf][1]);
        }
    }

    // epilogue
    #pragma unroll
    for (int mf = 0; mf < 4; ++mf) {
        #pragma unroll
        for (int nf = 0; nf < 4; ++nf) {
            int m = m0 + wm * 64 + mf * 16 + g;
            int n = n0 + wn * 32 + nf * 8 + 2 * kq;
            float bn0 = bias[n], bn1 = bias[n + 1];
            #pragma unroll
            for (int half = 0; half < 2; ++half) {
                int mm = m + half * 8;
                float v0 = acc[mf][nf][half * 2 + 0] + bn0;
                float v1 = acc[mf][nf][half * 2 + 1] + bn1;
                int bb = mm >> 11, s = mm & 2047;
                if (permuted) {
                    int h = n >> 6, dk = n & 63;
                    float2* dst = reinterpret_cast<float2*>(
                        &C[((size_t)(bb * HH + h) * SS + s) * DK + dk]);
                    *dst = make_float2(round_tf32(v0), round_tf32(v1));
                } else {
                    float2* dst = reinterpret_cast<float2*>(&C[(size_t)mm * DD + n]);
                    *dst = make_float2(v0, v1);
                }
            }
        }
    }
}

__global__ __launch_bounds__(256, 2) void qkv_proj_kernel(
    const float* __restrict__ bq, const float* __restrict__ bk, const float* __restrict__ bv)
{
    int w = blockIdx.z;
    const float* A  = (w == 0) ? g_cq : (w == 1) ? g_ck : g_cv;
    const float* Wt = (w == 0) ? g_wq : (w == 1) ? g_wk : g_wv;
    const float* bi = (w == 0) ? bq : (w == 1) ? bk : bv;
    float* C        = (w == 0) ? g_q : (w == 1) ? g_k : g_v;
    gemm_tf32(A, Wt, bi, C, true);
}

__global__ __launch_bounds__(256, 2) void out_proj_kernel(
    const float* __restrict__ bo, float* __restrict__ out)
{
    gemm_tf32(g_x, g_wo, bo, out, false);
}

// ---------------- banded attention (tf32 mma + ldmatrix, 512 threads) --------
#define KW  192
#define QST 68
#define KST 68
#define VST 72
#define PST 196
#define SMEM_ATTN ((64*QST + KW*KST + KW*VST + 64*PST) * 4)   // 175104 B

__global__ __launch_bounds__(512) void attn_kernel(float* __restrict__ attn_out)
{
    extern __shared__ float sm[];
    float* Qs = sm;                       // 64 x QST
    float* Ks = Qs + 64 * QST;            // 192 x KST
    float* Vs = Ks + KW * KST;            // 192 x VST
    float* Ps = Vs + KW * VST;            // 64 x PST
    __shared__ float pmax_[4][64];
    __shared__ float psum_[4][64];

    const int tid = threadIdx.x;
    const int bh  = blockIdx.y;
    const int i0  = blockIdx.x * 64;
    const int b   = bh >> 4, h = bh & 15;
    const int kg0 = i0 - HALF;

    const float* Qg = g_q + (size_t)bh * SS * DK;
    const float* Kg = g_k + (size_t)bh * SS * DK;
    const float* Vg = g_v + (size_t)bh * SS * DK;

    #pragma unroll
    for (int i = 0; i < 2; i++) {
        int f = tid + i * 512;
        int r = f >> 4, c = (f & 15) << 2;
        float4 v = *reinterpret_cast<const float4*>(&Qg[(size_t)(i0 + r) * DK + c]);
        *reinterpret_cast<float4*>(&Qs[r * QST + c]) = v;
    }
    #pragma unroll
    for (int i = 0; i < 6; i++) {
        int f = tid + i * 512;
        int r = f >> 4, c = (f & 15) << 2;
        int gr = kg0 + r;
        float4 kv = make_float4(0.f, 0.f, 0.f, 0.f);
        float4 vv = kv;
        if (gr >= 0 && gr < SS) {
            kv = *reinterpret_cast<const float4*>(&Kg[(size_t)gr * DK + c]);
            vv = *reinterpret_cast<const float4*>(&Vg[(size_t)gr * DK + c]);
        }
        *reinterpret_cast<float4*>(&Ks[r * KST + c]) = kv;
        *reinterpret_cast<float4*>(&Vs[r * VST + c]) = vv;
    }
    __syncthreads();

    const int lane = tid & 31, warp = tid >> 5;
    const int g  = lane >> 2;
    const int kq = lane & 3;
    const int wm = warp >> 2;
    const int nq = warp & 3;
    const int m0w = wm * 16;
    const int n0w = nq * 48;

    const int tIdx = lane >> 3;
    const int tRow = lane & 7;
    const unsigned qa_base = cvta_sh(Qs) +
        ((unsigned)((m0w + tRow + (tIdx & 1) * 8) * QST + (tIdx >> 1) * 4) << 2);
    const unsigned kb_base = cvta_sh(Ks) +
        ((unsigned)((n0w + tRow + (tIdx >> 1) * 8) * KST + (tIdx & 1) * 4) << 2);
    const unsigned pa_base = cvta_sh(Ps) +
        ((unsigned)((m0w + tRow + (tIdx & 1) * 8) * PST + (tIdx >> 1) * 4) << 2);

    float sacc[6][4];
    #pragma unroll
    for (int nt = 0; nt < 6; nt++)
        #pragma unroll
        for (int e = 0; e < 4; e++) sacc[nt][e] = 0.f;

    #pragma unroll
    for (int k0 = 0; k0 < DK; k0 += 8) {
        unsigned a0, a1, a2, a3;
        LDSM4(a0, a1, a2, a3, qa_base + (unsigned)(k0 * 4));
        unsigned bfr[6][2];
        #pragma unroll
        for (int p = 0; p < 3; ++p)
            LDSM4(bfr[2*p][0], bfr[2*p][1], bfr[2*p+1][0], bfr[2*p+1][1],
                  kb_base + (unsigned)(p * 16 * KST * 4 + k0 * 4));
        #pragma unroll
        for (int nt = 0; nt < 6; nt++)
            MMA_TF32(sacc[nt], a0, a1, a2, a3, bfr[nt][0], bfr[nt][1]);
    }

    const int r0 = m0w + g, r1 = m0w + 8 + g;
    float mx0 = -INFINITY, mx1 = -INFINITY;
    #pragma unroll
    for (int nt = 0; nt < 6; nt++) {
        #pragma unroll
        for (int e = 0; e < 4; e++) {
            int col = n0w + nt * 8 + 2 * kq + (e & 1);
            int rl  = (e < 2) ? r0 : r1;
            int j   = kg0 + col;
            bool ok = (col >= rl) && (col <= rl + 128) && (j >= 0) && (j < SS);
            float vv = ok ? sacc[nt][e] * 0.125f : -INFINITY;
            sacc[nt][e] = vv;
            if (e < 2) mx0 = fmaxf(mx0, vv); else mx1 = fmaxf(mx1, vv);
        }
    }
    #pragma unroll
    for (int o = 1; o < 4; o <<= 1) {
        mx0 = fmaxf(mx0, __shfl_xor_sync(0xffffffffu, mx0, o));
        mx1 = fmaxf(mx1, __shfl_xor_sync(0xffffffffu, mx1, o));
    }
    if (kq == 0) { pmax_[nq][r0] = mx0; pmax_[nq][r1] = mx1; }
    __syncthreads();
    float M0 = fmaxf(fmaxf(pmax_[0][r0], pmax_[1][r0]), fmaxf(pmax_[2][r0], pmax_[3][r0]));
    float M1 = fmaxf(fmaxf(pmax_[0][r1], pmax_[1][r1]), fmaxf(pmax_[2][r1], pmax_[3][r1]));

    float s0 = 0.f, s1 = 0.f;
    #pragma unroll
    for (int nt = 0; nt < 6; nt++) {
        float e0 = __expf(sacc[nt][0] - M0);
        float e1 = __expf(sacc[nt][1] - M0);
        float e2 = __expf(sacc[nt][2] - M1);
        float e3 = __expf(sacc[nt][3] - M1);
        sacc[nt][0] = e0; sacc[nt][1] = e1; sacc[nt][2] = e2; sacc[nt][3] = e3;
        s0 += e0 + e1; s1 += e2 + e3;
    }
    #pragma unroll
    for (int o = 1; o < 4; o <<= 1) {
        s0 += __shfl_xor_sync(0xffffffffu, s0, o);
        s1 += __shfl_xor_sync(0xffffffffu, s1, o);
    }
    if (kq == 0) { psum_[nq][r0] = s0; psum_[nq][r1] = s1; }
    __syncthreads();
    float inv0 = 1.0f / (psum_[0][r0] + psum_[1][r0] + psum_[2][r0] + psum_[3][r0]);
    float inv1 = 1.0f / (psum_[0][r1] + psum_[1][r1] + psum_[2][r1] + psum_[3][r1]);

    #pragma unroll
    for (int nt = 0; nt < 6; nt++) {
        int c = n0w + nt * 8 + 2 * kq;
        *reinterpret_cast<float2*>(&Ps[r0 * PST + c]) = make_float2(
            round_tf32(sacc[nt][0] * inv0), round_tf32(sacc[nt][1] * inv0));
        *reinterpret_cast<float2*>(&Ps[r1 * PST + c]) = make_float2(
            round_tf32(sacc[nt][2] * inv1), round_tf32(sacc[nt][3] * inv1));
    }
    __syncthreads();

    float pv[2][4];
    #pragma unroll
    for (int nt = 0; nt < 2; nt++)
        #pragma unroll
        for (int e = 0; e < 4; e++) pv[nt][e] = 0.f;

    const int n0v = nq * 16;
    #pragma unroll 1
    for (int kt = wm * 2; kt <= wm * 2 + 17; ++kt) {
        int k0 = kt * 8;
        unsigned a0, a1, a2, a3;
        LDSM4(a0, a1, a2, a3, pa_base + (unsigned)(k0 * 4));
        #pragma unroll
        for (int nt = 0; nt < 2; nt++) {
            unsigned b0 = __float_as_uint(Vs[(k0 + kq) * VST + n0v + nt * 8 + g]);
            unsigned b1 = __float_as_uint(Vs[(k0 + kq + 4) * VST + n0v + nt * 8 + g]);
            MMA_TF32(pv[nt], a0, a1, a2, a3, b0, b1);
        }
    }

    {
        float* xo0 = &g_x[((size_t)b * SS + (i0 + r0)) * DD + h * DK + n0v];
        float* xo1 = &g_x[((size_t)b * SS + (i0 + r1)) * DD + h * DK + n0v];
        #pragma unroll
        for (int nt = 0; nt < 2; nt++) {
            int c = nt * 8 + 2 * kq;
            *reinterpret_cast<float2*>(&xo0[c]) =
                make_float2(round_tf32(pv[nt][0]), round_tf32(pv[nt][1]));
            *reinterpret_cast<float2*>(&xo1[c]) =
                make_float2(round_tf32(pv[nt][2]), round_tf32(pv[nt][3]));
        }
    }

    // ---- write band of attn matrix (fill kernel never touches the band) ----
    for (int idx = tid; idx < 64 * 129; idx += 512) {
        int r = idx / 129;
        int t = idx - r * 129;
        int qg = i0 + r;
        int j  = qg - HALF + t;
        if (j >= 0 && j < SS)
            attn_out[((size_t)bh * SS + qg) * SS + j] = Ps[r * PST + r + t];
    }
}

// ---------------- launch -----------------------------------------------------
extern "C" void kernel_launch(void* const* d_in, const int* in_sizes, int n_in,
                              void* d_out, int out_size)
{
    const float* query = (const float*)d_in[0];
    const float* key   = (const float*)d_in[1];
    const float* value = (const float*)d_in[2];
    const float* Wq    = (const float*)d_in[3];
    const float* bq    = (const float*)d_in[4];
    const float* Wk    = (const float*)d_in[5];
    const float* bk    = (const float*)d_in[6];
    const float* Wv    = (const float*)d_in[7];
    const float* bv    = (const float*)d_in[8];
    const float* Wo    = (const float*)d_in[9];
    const float* bo    = (const float*)d_in[10];

    float* out  = (float*)d_out;
    float* attn = out + (size_t)BB * SS * DD;

    static cudaStream_t s_fill = nullptr;
    static cudaEvent_t  ev_fork = nullptr, ev_join = nullptr;
    if (s_fill == nullptr) {
        cudaStreamCreateWithFlags(&s_fill, cudaStreamNonBlocking);
        cudaEventCreateWithFlags(&ev_fork, cudaEventDisableTiming);
        cudaEventCreateWithFlags(&ev_join, cudaEventDisableTiming);
    }

    cudaFuncSetAttribute(qkv_proj_kernel, cudaFuncAttributeMaxDynamicSharedMemorySize, SMEM_GEMM);
    cudaFuncSetAttribute(out_proj_kernel, cudaFuncAttributeMaxDynamicSharedMemorySize, SMEM_GEMM);
    cudaFuncSetAttribute(attn_kernel,     cudaFuncAttributeMaxDynamicSharedMemorySize, SMEM_ATTN);

    // fork: band-skipping fill runs concurrently with the ENTIRE pipeline
    cudaEventRecord(ev_fork, 0);
    cudaStreamWaitEvent(s_fill, ev_fork, 0);
    fill_zero_kernel<<<FILL_BLOCKS, 256, 0, s_fill>>>(attn);
    cudaEventRecord(ev_join, s_fill);

    // fused prep: tf32-round inputs + transpose/round weights
    prep_kernel<<<dim3(4096, 7), 256>>>(query, key, value, Wq, Wk, Wv, Wo);

    // Q/K/V projections (lean 3-stage pipelined TF32 mma)
    qkv_proj_kernel<<<dim3(8, 32, 3), 256, SMEM_GEMM>>>(bq, bk, bv);

    // banded attention (band writes are disjoint from the fill)
    attn_kernel<<<dim3(SS / 64, BB * HH), 512, SMEM_ATTN>>>(attn);

    // output projection
    out_proj_kernel<<<dim3(8, 32), 256, SMEM_GEMM>>>(bo, out);

    // join: main stream waits for the background fill, then a terminator node
    // anchors the dependency inside the captured graph
    cudaStreamWaitEvent(0, ev_join, 0);
    join_kernel<<<1, 32>>>();
}

// round 16
// speedup vs baseline: 1.1640x; 1.1640x over previous
#include <cuda_runtime.h>
#include <cuda_bf16.h>
#include <math.h>

// Problem constants
#define BB   2
#define SS   2048
#define DD   1024
#define HH   16
#define DK   64
#define HALF 64

// ---------------- scratch (device globals; no runtime allocation) ----------
__device__ float g_q[BB*HH*SS*DK];   // [B,H,S,DK] (tf32-rounded)
__device__ float g_k[BB*HH*SS*DK];
__device__ float g_v[BB*HH*SS*DK];
__device__ float g_x[BB*SS*DD];      // [B,S,D] attention output (tf32-rounded)
__device__ float g_cq[BB*SS*DD];     // tf32-rounded inputs
__device__ float g_ck[BB*SS*DD];
__device__ float g_cv[BB*SS*DD];
__device__ float g_wq[DD*DD];        // tf32-rounded transposed weights [n][k]
__device__ float g_wk[DD*DD];
__device__ float g_wv[DD*DD];
__device__ float g_wo[DD*DD];

// ---------------- helpers ----------------------------------------------------
__device__ __forceinline__ unsigned cvta_sh(const void* p) {
    return (unsigned)__cvta_generic_to_shared(p);
}
__device__ __forceinline__ unsigned cvt_tf32(float x) {
    unsigned r; asm("cvt.rna.tf32.f32 %0, %1;" : "=r"(r) : "f"(x)); return r;
}
__device__ __forceinline__ float round_tf32(float x) {
    return __uint_as_float(cvt_tf32(x));
}
#define CP_ASYNC16(saddr, gaddr) \
    asm volatile("cp.async.cg.shared.global [%0], [%1], 16;\n" :: "r"(saddr), "l"(gaddr))
#define CP_COMMIT() asm volatile("cp.async.commit_group;\n" ::)
#define CP_WAIT(N)  asm volatile("cp.async.wait_group %0;\n" :: "n"(N))

#define MMA_TF32(ac, a0,a1,a2,a3, b0,b1) \
    asm volatile( \
        "mma.sync.aligned.m16n8k8.row.col.f32.tf32.tf32.f32 " \
        "{%0,%1,%2,%3}, {%4,%5,%6,%7}, {%8,%9}, {%0,%1,%2,%3};" \
        : "+f"((ac)[0]), "+f"((ac)[1]), "+f"((ac)[2]), "+f"((ac)[3]) \
        : "r"(a0), "r"(a1), "r"(a2), "r"(a3), "r"(b0), "r"(b1))

#define LDSM4(r0,r1,r2,r3, addr) \
    asm volatile("ldmatrix.sync.aligned.m8n8.x4.shared.b16 {%0,%1,%2,%3}, [%4];" \
        : "=r"(r0), "=r"(r1), "=r"(r2), "=r"(r3) : "r"(addr))

// ---------------- fused prep: round inputs + transpose/round weights ---------
__global__ __launch_bounds__(256) void prep_kernel(
    const float* __restrict__ q, const float* __restrict__ k, const float* __restrict__ v,
    const float* __restrict__ Wq, const float* __restrict__ Wk,
    const float* __restrict__ Wv, const float* __restrict__ Wo)
{
    __shared__ float tile[32][33];
    int z = blockIdx.y;
    if (z < 3) {
        const float* src = (z == 0) ? q : (z == 1) ? k : v;
        float* dst = (z == 0) ? g_cq : (z == 1) ? g_ck : g_cv;
        size_t i = (size_t)blockIdx.x * 256 + threadIdx.x;
        float4 x = reinterpret_cast<const float4*>(src)[i];
        x.x = round_tf32(x.x); x.y = round_tf32(x.y);
        x.z = round_tf32(x.z); x.w = round_tf32(x.w);
        reinterpret_cast<float4*>(dst)[i] = x;
    } else {
        if (blockIdx.x >= 1024) return;
        int w = z - 3;
        const float* W = (w == 0) ? Wq : (w == 1) ? Wk : (w == 2) ? Wv : Wo;
        float* Wt      = (w == 0) ? g_wq : (w == 1) ? g_wk : (w == 2) ? g_wv : g_wo;
        int k0 = (blockIdx.x >> 5) * 32, n0 = (blockIdx.x & 31) * 32;
        int tx = threadIdx.x & 31, ty = threadIdx.x >> 5;
        #pragma unroll
        for (int j = 0; j < 32; j += 8)
            tile[ty + j][tx] = W[(size_t)(k0 + ty + j) * DD + n0 + tx];
        __syncthreads();
        #pragma unroll
        for (int j = 0; j < 32; j += 8)
            Wt[(size_t)(n0 + ty + j) * DD + k0 + tx] = round_tf32(tile[tx][ty + j]);
    }
}

// ---------------- TF32 GEMM: block 128x128, warp 64x32, BK=32, 3 stages ------
#define AS_STRIDE 36
#define BS_STRIDE 36
#define AS_STAGE  (128 * AS_STRIDE)
#define BS_STAGE  (128 * BS_STRIDE)
#define NSTAGE 3
#define SMEM_GEMM ((NSTAGE * (AS_STAGE + BS_STAGE)) * 4)   // 110592 B
#define NT (DD / 32)                                        // 32 k-iterations

#define FILL_TOTAL4 ((size_t)BB * HH * SS * SS / 4)    // 33554432 float4
#define FILL_THREADS ((size_t)768 * 256)

__device__ __forceinline__ void gemm_load_stage(
    const float* __restrict__ A, const float* __restrict__ Wt,
    float* As, float* Bs, int stage, int k0, int m0, int n0, int tid)
{
    float* Ad = As + stage * AS_STAGE;
    float* Bd = Bs + stage * BS_STAGE;
    #pragma unroll
    for (int i = 0; i < 4; i++) {
        int f = tid + i * 256;
        int r = f >> 3, c4 = f & 7;
        CP_ASYNC16(cvta_sh(&Ad[r * AS_STRIDE + c4 * 4]),
                   &A[(size_t)(m0 + r) * DD + k0 + c4 * 4]);
    }
    #pragma unroll
    for (int i = 0; i < 4; i++) {
        int f = tid + i * 256;
        int r = f >> 3, c4 = f & 7;
        CP_ASYNC16(cvta_sh(&Bd[r * BS_STRIDE + c4 * 4]),
                   &Wt[(size_t)(n0 + r) * DD + k0 + c4 * 4]);
    }
    CP_COMMIT();
}

template <bool FILL>
__device__ __forceinline__ void gemm_tf32(const float* __restrict__ A,
                                          const float* __restrict__ Wt,
                                          const float* __restrict__ bias,
                                          float* __restrict__ C,
                                          bool permuted,
                                          float4* __restrict__ zdst,
                                          size_t gtid)
{
    extern __shared__ float sm[];
    float* As = sm;
    float* Bs = sm + NSTAGE * AS_STAGE;

    const int tid  = threadIdx.x;
    const int lane = tid & 31;
    const int wid  = tid >> 5;
    const int wm   = wid >> 2;
    const int wn   = wid & 3;
    const int m0   = blockIdx.y * 128;
    const int n0   = blockIdx.x * 128;
    const int g    = lane >> 2;
    const int kq   = lane & 3;

    const int tIdx = lane >> 3;
    const int tRow = lane & 7;
    const unsigned a_base = cvta_sh(As) +
        (((wm * 64 + tRow + (tIdx & 1) * 8) * AS_STRIDE + (tIdx >> 1) * 4) << 2);
    const unsigned b_base = cvta_sh(Bs) +
        (((wn * 32 + tRow + (tIdx >> 1) * 8) * BS_STRIDE + (tIdx & 1) * 4) << 2);

    float acc[4][4][4];
    #pragma unroll
    for (int i = 0; i < 4; i++)
        #pragma unroll
        for (int j = 0; j < 4; j++)
            #pragma unroll
            for (int e = 0; e < 4; e++) acc[i][j][e] = 0.f;

    gemm_load_stage(A, Wt, As, Bs, 0, 0, m0, n0, tid);
    gemm_load_stage(A, Wt, As, Bs, 1, 32, m0, n0, tid);

    const float4 z4 = make_float4(0.f, 0.f, 0.f, 0.f);

    #pragma unroll 1
    for (int t = 0; t < NT; ++t) {
        if (t < NT - 1) { CP_WAIT(1); } else { CP_WAIT(0); }
        __syncthreads();

        if (t + 2 < NT)
            gemm_load_stage(A, Wt, As, Bs, (t + 2) % NSTAGE, (t + 2) * 32, m0, n0, tid);

        if (FILL) {
            #pragma unroll
            for (int u = 0; u < 6; ++u) {
                size_t idx = (size_t)(t * 6 + u) * FILL_THREADS + gtid;
                if (idx < FILL_TOTAL4) __stcs(&zdst[idx], z4);
            }
        }

        const int stg = t % NSTAGE;
        const unsigned aoff = a_base + (unsigned)(stg * AS_STAGE * 4);
        const unsigned boff = b_base + (unsigned)(stg * BS_STAGE * 4);

        #pragma unroll
        for (int kk = 0; kk < 4; ++kk) {
            unsigned a[4][4], b[4][2];
            #pragma unroll
            for (int mf = 0; mf < 4; ++mf)
                LDSM4(a[mf][0], a[mf][1], a[mf][2], a[mf][3],
                      aoff + (unsigned)(mf * 16 * AS_STRIDE * 4 + kk * 32));
            #pragma unroll
            for (int p = 0; p < 2; ++p)
                LDSM4(b[2*p][0], b[2*p][1], b[2*p+1][0], b[2*p+1][1],
                      boff + (unsigned)(p * 16 * BS_STRIDE * 4 + kk * 32));
            #pragma unroll
            for (int mf = 0; mf < 4; ++mf)
                #pragma unroll
                for (int nf = 0; nf < 4; ++nf)
                    MMA_TF32(acc[mf][nf], a[mf][0], a[mf][1], a[mf][2], a[mf][3],
                             b[nf][0], b[nf][1]);
        }
    }

    // epilogue (permuted outputs feed tf32 mma consumers -> round here, RNA)
    #pragma unroll
    for (int mf = 0; mf < 4; ++mf) {
        #pragma unroll
        for (int nf = 0; nf < 4; ++nf) {
            int m = m0 + wm * 64 + mf * 16 + g;
            int n = n0 + wn * 32 + nf * 8 + 2 * kq;
            float bn0 = bias[n], bn1 = bias[n + 1];
            #pragma unroll
            for (int half = 0; half < 2; ++half) {
                int mm = m + half * 8;
                float v0 = acc[mf][nf][half * 2 + 0] + bn0;
                float v1 = acc[mf][nf][half * 2 + 1] + bn1;
                int bb = mm >> 11, s = mm & 2047;
                if (permuted) {
                    int h = n >> 6, dk = n & 63;
                    float2* dst = reinterpret_cast<float2*>(
                        &C[((size_t)(bb * HH + h) * SS + s) * DK + dk]);
                    *dst = make_float2(round_tf32(v0), round_tf32(v1));
                } else {
                    float2* dst = reinterpret_cast<float2*>(&C[(size_t)mm * DD + n]);
                    *dst = make_float2(v0, v1);
                }
            }
        }
    }
}

__global__ __launch_bounds__(256, 2) void qkv_proj_kernel(
    const float* __restrict__ bq, const float* __restrict__ bk, const float* __restrict__ bv,
    float* __restrict__ zattn)
{
    int w = blockIdx.z;
    const float* A  = (w == 0) ? g_cq : (w == 1) ? g_ck : g_cv;
    const float* Wt = (w == 0) ? g_wq : (w == 1) ? g_wk : g_wv;
    const float* bi = (w == 0) ? bq : (w == 1) ? bk : bv;
    float* C        = (w == 0) ? g_q : (w == 1) ? g_k : g_v;
    const int bid   = blockIdx.x + blockIdx.y * 8 + blockIdx.z * 256;   // 0..767
    size_t gtid     = (size_t)bid * 256 + threadIdx.x;
    gemm_tf32<true>(A, Wt, bi, C, true, reinterpret_cast<float4*>(zattn), gtid);
}

__global__ __launch_bounds__(256, 2) void out_proj_kernel(
    const float* __restrict__ bo, float* __restrict__ out)
{
    gemm_tf32<false>(g_x, g_wo, bo, out, false, nullptr, 0);
}

// ---------------- banded attention (tf32 mma + ldmatrix, 512 threads) --------
#define KW  192
#define QST 68
#define KST 68
#define VST 72
#define PST 196
#define SMEM_ATTN ((64*QST + KW*KST + KW*VST + 64*PST) * 4)   // 175104 B

__global__ __launch_bounds__(512) void attn_kernel(float* __restrict__ attn_out)
{
    extern __shared__ float sm[];
    float* Qs = sm;                       // 64 x QST
    float* Ks = Qs + 64 * QST;            // 192 x KST
    float* Vs = Ks + KW * KST;            // 192 x VST
    float* Ps = Vs + KW * VST;            // 64 x PST
    __shared__ float pmax_[4][64];
    __shared__ float psum_[4][64];

    const int tid = threadIdx.x;
    const int bh  = blockIdx.y;
    const int i0  = blockIdx.x * 64;
    const int b   = bh >> 4, h = bh & 15;
    const int kg0 = i0 - HALF;

    const float* Qg = g_q + (size_t)bh * SS * DK;
    const float* Kg = g_k + (size_t)bh * SS * DK;
    const float* Vg = g_v + (size_t)bh * SS * DK;

    #pragma unroll
    for (int i = 0; i < 2; i++) {
        int f = tid + i * 512;
        int r = f >> 4, c = (f & 15) << 2;
        float4 v = *reinterpret_cast<const float4*>(&Qg[(size_t)(i0 + r) * DK + c]);
        *reinterpret_cast<float4*>(&Qs[r * QST + c]) = v;
    }
    #pragma unroll
    for (int i = 0; i < 6; i++) {
        int f = tid + i * 512;
        int r = f >> 4, c = (f & 15) << 2;
        int gr = kg0 + r;
        float4 kv = make_float4(0.f, 0.f, 0.f, 0.f);
        float4 vv = kv;
        if (gr >= 0 && gr < SS) {
            kv = *reinterpret_cast<const float4*>(&Kg[(size_t)gr * DK + c]);
            vv = *reinterpret_cast<const float4*>(&Vg[(size_t)gr * DK + c]);
        }
        *reinterpret_cast<float4*>(&Ks[r * KST + c]) = kv;
        *reinterpret_cast<float4*>(&Vs[r * VST + c]) = vv;
    }
    __syncthreads();

    const int lane = tid & 31, warp = tid >> 5;
    const int g  = lane >> 2;
    const int kq = lane & 3;
    const int wm = warp >> 2;          // 0..3 -> 16-row m tile
    const int nq = warp & 3;           // 0..3 -> 48-key quarter
    const int m0w = wm * 16;
    const int n0w = nq * 48;

    const int tIdx = lane >> 3;
    const int tRow = lane & 7;
    const unsigned qa_base = cvta_sh(Qs) +
        ((unsigned)((m0w + tRow + (tIdx & 1) * 8) * QST + (tIdx >> 1) * 4) << 2);
    const unsigned kb_base = cvta_sh(Ks) +
        ((unsigned)((n0w + tRow + (tIdx >> 1) * 8) * KST + (tIdx & 1) * 4) << 2);
    const unsigned pa_base = cvta_sh(Ps) +
        ((unsigned)((m0w + tRow + (tIdx & 1) * 8) * PST + (tIdx >> 1) * 4) << 2);

    float sacc[6][4];
    #pragma unroll
    for (int nt = 0; nt < 6; nt++)
        #pragma unroll
        for (int e = 0; e < 4; e++) sacc[nt][e] = 0.f;

    // dead-quarter skip: quarter [n0w, n0w+47] vs band-union [m0w, m0w+143]
    const bool quarter_live = !(n0w > m0w + 15 + 128 || n0w + 47 < m0w);
    if (quarter_live) {
        #pragma unroll
        for (int k0 = 0; k0 < DK; k0 += 8) {
            unsigned a0, a1, a2, a3;
            LDSM4(a0, a1, a2, a3, qa_base + (unsigned)(k0 * 4));
            unsigned bfr[6][2];
            #pragma unroll
            for (int p = 0; p < 3; ++p)
                LDSM4(bfr[2*p][0], bfr[2*p][1], bfr[2*p+1][0], bfr[2*p+1][1],
                      kb_base + (unsigned)(p * 16 * KST * 4 + k0 * 4));
            #pragma unroll
            for (int nt = 0; nt < 6; nt++)
                MMA_TF32(sacc[nt], a0, a1, a2, a3, bfr[nt][0], bfr[nt][1]);
        }
    }

    const int r0 = m0w + g, r1 = m0w + 8 + g;
    float mx0 = -INFINITY, mx1 = -INFINITY;
    #pragma unroll
    for (int nt = 0; nt < 6; nt++) {
        #pragma unroll
        for (int e = 0; e < 4; e++) {
            int col = n0w + nt * 8 + 2 * kq + (e & 1);
            int rl  = (e < 2) ? r0 : r1;
            int j   = kg0 + col;
            bool ok = (col >= rl) && (col <= rl + 128) && (j >= 0) && (j < SS);
            float vv = ok ? sacc[nt][e] * 0.125f : -INFINITY;
            sacc[nt][e] = vv;
            if (e < 2) mx0 = fmaxf(mx0, vv); else mx1 = fmaxf(mx1, vv);
        }
    }
    #pragma unroll
    for (int o = 1; o < 4; o <<= 1) {
        mx0 = fmaxf(mx0, __shfl_xor_sync(0xffffffffu, mx0, o));
        mx1 = fmaxf(mx1, __shfl_xor_sync(0xffffffffu, mx1, o));
    }
    if (kq == 0) { pmax_[nq][r0] = mx0; pmax_[nq][r1] = mx1; }
    __syncthreads();
    float M0 = fmaxf(fmaxf(pmax_[0][r0], pmax_[1][r0]), fmaxf(pmax_[2][r0], pmax_[3][r0]));
    float M1 = fmaxf(fmaxf(pmax_[0][r1], pmax_[1][r1]), fmaxf(pmax_[2][r1], pmax_[3][r1]));

    float s0 = 0.f, s1 = 0.f;
    #pragma unroll
    for (int nt = 0; nt < 6; nt++) {
        float e0 = __expf(sacc[nt][0] - M0);
        float e1 = __expf(sacc[nt][1] - M0);
        float e2 = __expf(sacc[nt][2] - M1);
        float e3 = __expf(sacc[nt][3] - M1);
        sacc[nt][0] = e0; sacc[nt][1] = e1; sacc[nt][2] = e2; sacc[nt][3] = e3;
        s0 += e0 + e1; s1 += e2 + e3;
    }
    #pragma unroll
    for (int o = 1; o < 4; o <<= 1) {
        s0 += __shfl_xor_sync(0xffffffffu, s0, o);
        s1 += __shfl_xor_sync(0xffffffffu, s1, o);
    }
    if (kq == 0) { psum_[nq][r0] = s0; psum_[nq][r1] = s1; }
    __syncthreads();
    float inv0 = 1.0f / (psum_[0][r0] + psum_[1][r0] + psum_[2][r0] + psum_[3][r0]);
    float inv1 = 1.0f / (psum_[0][r1] + psum_[1][r1] + psum_[2][r1] + psum_[3][r1]);

    // store P pre-rounded to tf32 (same numerics as cvt at PV consumer)
    #pragma unroll
    for (int nt = 0; nt < 6; nt++) {
        int c = n0w + nt * 8 + 2 * kq;
        *reinterpret_cast<float2*>(&Ps[r0 * PST + c]) = make_float2(
            round_tf32(sacc[nt][0] * inv0), round_tf32(sacc[nt][1] * inv0));
        *reinterpret_cast<float2*>(&Ps[r1 * PST + c]) = make_float2(
            round_tf32(sacc[nt][2] * inv1), round_tf32(sacc[nt][3] * inv1));
    }
    __syncthreads();

    float pv[2][4];
    #pragma unroll
    for (int nt = 0; nt < 2; nt++)
        #pragma unroll
        for (int e = 0; e < 4; e++) pv[nt][e] = 0.f;

    const int n0v = nq * 16;
    #pragma unroll 1
    for (int kt = wm * 2; kt <= wm * 2 + 17; ++kt) {
        int k0 = kt * 8;
        unsigned a0, a1, a2, a3;
        LDSM4(a0, a1, a2, a3, pa_base + (unsigned)(k0 * 4));
        #pragma unroll
        for (int nt = 0; nt < 2; nt++) {
            unsigned b0 = __float_as_uint(Vs[(k0 + kq) * VST + n0v + nt * 8 + g]);
            unsigned b1 = __float_as_uint(Vs[(k0 + kq + 4) * VST + n0v + nt * 8 + g]);
            MMA_TF32(pv[nt], a0, a1, a2, a3, b0, b1);
        }
    }

    {
        float* xo0 = &g_x[((size_t)b * SS + (i0 + r0)) * DD + h * DK + n0v];
        float* xo1 = &g_x[((size_t)b * SS + (i0 + r1)) * DD + h * DK + n0v];
        #pragma unroll
        for (int nt = 0; nt < 2; nt++) {
            int c = nt * 8 + 2 * kq;
            *reinterpret_cast<float2*>(&xo0[c]) =
                make_float2(round_tf32(pv[nt][0]), round_tf32(pv[nt][1]));
            *reinterpret_cast<float2*>(&xo1[c]) =
                make_float2(round_tf32(pv[nt][2]), round_tf32(pv[nt][3]));
        }
    }

    // ---- band write: warp-per-4-rows, lanes sweep the 129-col window -------
    // (no integer division; coalesced 32-wide segments; streaming stores)
    {
        float* base = attn_out + (size_t)bh * SS * SS;
        #pragma unroll
        for (int rr = 0; rr < 4; ++rr) {
            int r  = warp * 4 + rr;
            int qg = i0 + r;
            const float* pr = &Ps[r * PST + r];
            float* orow = &base[(size_t)qg * SS + qg - HALF];
            #pragma unroll
            for (int t5 = 0; t5 < 5; ++t5) {
                int t = lane + t5 * 32;
                int j = qg - HALF + t;
                if (t <= 128 && j >= 0 && j < SS)
                    __stcs(&orow[t], pr[t]);
            }
        }
    }
}

// ---------------- launch -----------------------------------------------------
extern "C" void kernel_launch(void* const* d_in, const int* in_sizes, int n_in,
                              void* d_out, int out_size)
{
    const float* query = (const float*)d_in[0];
    const float* key   = (const float*)d_in[1];
    const float* value = (const float*)d_in[2];
    const float* Wq    = (const float*)d_in[3];
    const float* bq    = (const float*)d_in[4];
    const float* Wk    = (const float*)d_in[5];
    const float* bk    = (const float*)d_in[6];
    const float* Wv    = (const float*)d_in[7];
    const float* bv    = (const float*)d_in[8];
    const float* Wo    = (const float*)d_in[9];
    const float* bo    = (const float*)d_in[10];

    float* out  = (float*)d_out;
    float* attn = out + (size_t)BB * SS * DD;

    cudaFuncSetAttribute(qkv_proj_kernel, cudaFuncAttributeMaxDynamicSharedMemorySize, SMEM_GEMM);
    cudaFuncSetAttribute(out_proj_kernel, cudaFuncAttributeMaxDynamicSharedMemorySize, SMEM_GEMM);
    cudaFuncSetAttribute(attn_kernel,     cudaFuncAttributeMaxDynamicSharedMemorySize, SMEM_ATTN);

    // fused prep: tf32-round inputs + transpose/round weights
    prep_kernel<<<dim3(4096, 7), 256>>>(query, key, value, Wq, Wk, Wv, Wo);

    // Q/K/V projections (3-stage pipelined TF32 mma) + interleaved zero-fill
    qkv_proj_kernel<<<dim3(8, 32, 3), 256, SMEM_GEMM>>>(bq, bk, bv, attn);

    // banded attention
    attn_kernel<<<dim3(SS / 64, BB * HH), 512, SMEM_ATTN>>>(attn);

    // output projection
    out_proj_kernel<<<dim3(8, 32), 256, SMEM_GEMM>>>(bo, out);
}